// round 11
// baseline (speedup 1.0000x reference)
#include <cuda_runtime.h>
#include <cuda_bf16.h>
#include <cstdint>

// ---------------------------------------------------------------------------
// DGCNN forward. B=512, N=64, K=16, IN_CH=6.
// Fully DETERMINISTIC: no float atomicAdd anywhere (fixed-partition partials
// + fixed-order reductions). Edge GEMM2: 3xTF32 mma.sync, block=batch,
// 512 threads, 128-edge chunks, smem scatter-max (atomicMax = order-indep).
// ---------------------------------------------------------------------------
#define BB 512
#define NN 64
#define KK 16
#define NPTS (BB*NN)          // 32768
#define NEDGE (NPTS*KK)       // 524288
#define HCATC 448
#define EPSV 1e-5f

// ---------------- static scratch ----------------
__device__ float g_h0[NPTS*64];
__device__ float g_hcat[NPTS*HCATC];
__device__ float g_A[NPTS*256];
__device__ float g_Bp[NPTS*256];
__device__ int   g_nbr[NEDGE];
__device__ float g_wB[256*256];
__device__ uint32_t g_wH[256*256];
__device__ uint32_t g_wL[256*256];
__device__ float g_stats[4096];
__device__ float g_scale[2048];
__device__ float g_shift[2048];
__device__ float g_part[512*512];     // per-block stats partials (max P*2C)
__device__ float g_pooled[BB*896];
__device__ float g_z1[BB*512];
__device__ float g_z2[BB*256];

// ---------------- helpers ----------------
__device__ __forceinline__ unsigned encf(float x) {
    unsigned u = __float_as_uint(x);
    return (u & 0x80000000u) ? ~u : (u | 0x80000000u);
}
__device__ __forceinline__ float decf(unsigned u) {
    unsigned b = (u & 0x80000000u) ? (u & 0x7FFFFFFFu) : ~u;
    return __uint_as_float(b);
}
#define ENC_NEGINF 0x007FFFFFu   // encf(-inf)

__device__ __forceinline__ uint32_t f2tf32(float f) {
    uint32_t u; asm("cvt.rna.tf32.f32 %0, %1;" : "=r"(u) : "f"(f)); return u;
}
__device__ __forceinline__ void tf32_split(float x, uint32_t& hi, uint32_t& lo) {
    hi = f2tf32(x);
    lo = f2tf32(x - __uint_as_float(hi));
}
__device__ __forceinline__ void mma_tf32(float* c,
    uint32_t a0, uint32_t a1, uint32_t a2, uint32_t a3, uint32_t b0, uint32_t b1)
{
    asm volatile("mma.sync.aligned.m16n8k8.row.col.f32.tf32.tf32.f32 "
        "{%0,%1,%2,%3}, {%4,%5,%6,%7}, {%8,%9}, {%0,%1,%2,%3};"
        : "+f"(c[0]), "+f"(c[1]), "+f"(c[2]), "+f"(c[3])
        : "r"(a0), "r"(a1), "r"(a2), "r"(a3), "r"(b0), "r"(b1));
}

// wB = w1[0:Cin,:] - w1[Cin:2Cin,:]
__global__ void prep_wb(const float* __restrict__ w1, float* __restrict__ wB, int n) {
    int i = blockIdx.x*256 + threadIdx.x;
    if (i < n) wB[i] = w1[i] - w1[n + i];
}

// precompute tf32 hi/lo split of W
__global__ void split_w(const float* __restrict__ W, uint32_t* __restrict__ WH,
                        uint32_t* __restrict__ WL, int n) {
    int i = blockIdx.x*256 + threadIdx.x;
    if (i < n) {
        uint32_t h, l;
        tf32_split(W[i], h, l);
        WH[i] = h; WL[i] = l;
    }
}

// ---------------- deterministic column stats ----------------
// grid (C/32, P), block (32,8). Partition of rows fixed by blockIdx.y.
// Writes part[p*2C + c] (sum) and part[p*2C + C + c] (sumsq). No atomics.
__global__ void col_stats_part(const float* __restrict__ X, float* __restrict__ part,
                               int R, int C, int ld, int off)
{
    int c = blockIdx.x*32 + threadIdx.x;
    int P = gridDim.y;
    float s = 0.f, q = 0.f;
    for (int r = blockIdx.y*8 + threadIdx.y; r < R; r += P*8) {
        float v = X[(size_t)r*ld + off + c];
        s += v; q = fmaf(v, v, q);
    }
    __shared__ float ss[8][33], qq[8][33];
    ss[threadIdx.y][threadIdx.x] = s;
    qq[threadIdx.y][threadIdx.x] = q;
    __syncthreads();
    if (threadIdx.y == 0) {
        #pragma unroll
        for (int y = 1; y < 8; y++) { s += ss[y][threadIdx.x]; q += qq[y][threadIdx.x]; }
        part[(size_t)blockIdx.y*2*C + c]     = s;
        part[(size_t)blockIdx.y*2*C + C + c] = q;
    }
}

// stats[c] = sum over fixed order p=0..P-1 of part[p*n + c]
__global__ void reduce_part(const float* __restrict__ part, float* __restrict__ stats,
                            int n, int P)
{
    int c = blockIdx.x*128 + threadIdx.x;
    if (c >= n) return;
    float s = 0.f;
    for (int p = 0; p < P; p++) s += part[(size_t)p*n + c];
    stats[c] = s;
}

// ---------------- generic tiled GEMM: Y = X @ W (+bias), fp32 ----------------
__global__ void gemm_bias(const float* __restrict__ X, const float* __restrict__ W,
                          const float* __restrict__ bias, float* __restrict__ Y,
                          int R, int Ci, int Co, int ldx, int xoff, int ldy, int yoff)
{
    __shared__ float Xs[16][68];
    __shared__ float Ws[16][68];
    int row0 = blockIdx.y*64, col0 = blockIdx.x*64;
    int tid = threadIdx.x;
    float acc[4][4] = {};
    for (int k0 = 0; k0 < Ci; k0 += 16) {
        #pragma unroll
        for (int l = 0; l < 4; l++) {
            int i = tid + l*256;
            int r = i >> 4, kk = i & 15;
            int gr = row0 + r, gk = k0 + kk;
            Xs[kk][r] = (gr < R && gk < Ci) ? X[(size_t)gr*ldx + xoff + gk] : 0.f;
        }
        #pragma unroll
        for (int l = 0; l < 4; l++) {
            int i = tid + l*256;
            int kk = i >> 6, c = i & 63;
            int gk = k0 + kk, gc = col0 + c;
            Ws[kk][c] = (gk < Ci && gc < Co) ? W[(size_t)gk*Co + gc] : 0.f;
        }
        __syncthreads();
        int ty = tid >> 4, tx = tid & 15;
        #pragma unroll
        for (int kk = 0; kk < 16; kk++) {
            float4 a = *(const float4*)&Xs[kk][ty*4];
            float4 b = *(const float4*)&Ws[kk][tx*4];
            acc[0][0]=fmaf(a.x,b.x,acc[0][0]); acc[0][1]=fmaf(a.x,b.y,acc[0][1]);
            acc[0][2]=fmaf(a.x,b.z,acc[0][2]); acc[0][3]=fmaf(a.x,b.w,acc[0][3]);
            acc[1][0]=fmaf(a.y,b.x,acc[1][0]); acc[1][1]=fmaf(a.y,b.y,acc[1][1]);
            acc[1][2]=fmaf(a.y,b.z,acc[1][2]); acc[1][3]=fmaf(a.y,b.w,acc[1][3]);
            acc[2][0]=fmaf(a.z,b.x,acc[2][0]); acc[2][1]=fmaf(a.z,b.y,acc[2][1]);
            acc[2][2]=fmaf(a.z,b.z,acc[2][2]); acc[2][3]=fmaf(a.z,b.w,acc[2][3]);
            acc[3][0]=fmaf(a.w,b.x,acc[3][0]); acc[3][1]=fmaf(a.w,b.y,acc[3][1]);
            acc[3][2]=fmaf(a.w,b.z,acc[3][2]); acc[3][3]=fmaf(a.w,b.w,acc[3][3]);
        }
        __syncthreads();
    }
    int ty = tid >> 4, tx = tid & 15;
    #pragma unroll
    for (int i = 0; i < 4; i++) {
        int gr = row0 + ty*4 + i;
        if (gr >= R) continue;
        #pragma unroll
        for (int j = 0; j < 4; j++) {
            int gc = col0 + tx*4 + j;
            if (gc < Co) {
                float v = acc[i][j];
                if (bias) v += bias[gc];
                Y[(size_t)gr*ldy + yoff + gc] = v;
            }
        }
    }
}

// ---------------- edge GEMM2: 3xTF32 mma, block=batch, 512 threads ----------
// Block b: all 1024 edges of batch b, 8 chunks of 128 edges.
// Deterministic stats: lane-owned smem slots (no atomics), fixed-order warp
// combine, per-batch partials to g_part.
template<int CO>
__global__ void __launch_bounds__(512, 1)
edge_mma_batch(const float* __restrict__ A, const float* __restrict__ Bp,
               const int* __restrict__ nbr,
               const float* __restrict__ sc, const float* __restrict__ sh,
               const uint32_t* __restrict__ WH, const uint32_t* __restrict__ WL,
               float* __restrict__ part,
               float* __restrict__ hcat,
               int Cmid, int off)
{
    constexpr int NT  = CO/16;
    constexpr int WST = CO + 8;
    constexpr int XST = 132;
    constexpr int NW4 = CO/64;
    extern __shared__ uint32_t smem_u[];
    uint32_t* XsH = smem_u;                      // [16][132]
    uint32_t* XsL = XsH + 16*XST;                // [16][132]
    uint32_t* WsH = XsL + 16*XST;                // [16][WST]
    uint32_t* WsL = WsH + 16*WST;                // [16][WST]
    int*      nb  = (int*)(WsL + 16*WST);        // [1024]
    unsigned* maxbuf = (unsigned*)(nb + 1024);   // [64][CO]
    float*    redp = (float*)(maxbuf + 64*CO);   // [8][2*CO] per-rg partials

    int b = blockIdx.x;
    int tid = threadIdx.x;
    int wid = tid >> 5, lane = tid & 31;
    int rg = wid >> 1, ch = wid & 1;
    int lt = lane & 3, lg = lane >> 2;

    for (int i = tid; i < 1024; i += 512) nb[i] = nbr[b*1024 + i];
    for (int i = tid; i < 64*CO; i += 512) maxbuf[i] = ENC_NEGINF;
    for (int i = tid; i < 16*CO; i += 512) redp[i] = 0.f;
    __syncthreads();

    int xr = tid >> 2;            // 0..127: edge row in chunk
    int xc = (tid & 3) * 4;       // k offset 0,4,8,12
    int wk = tid >> 4;            // 0..15 (tid<256): W k-row
    int wc = (tid & 15) * (CO/16);

    for (int rc = 0; rc < 8; rc++) {
        float acc[NT][4];
        #pragma unroll
        for (int t = 0; t < NT; t++) { acc[t][0]=acc[t][1]=acc[t][2]=acc[t][3]=0.f; }

        int n_row = (b*1024 + rc*128 + xr) >> 4;
        int m_row = nb[rc*128 + xr];
        const float* Arow = A + (size_t)n_row*Cmid;
        const float* Brow = Bp + (size_t)m_row*Cmid;

        for (int k0 = 0; k0 < Cmid; k0 += 16) {
            float4 av = *(const float4*)(Arow + k0 + xc);
            float4 bv = *(const float4*)(Brow + k0 + xc);
            float4 s4 = *(const float4*)(sc + k0 + xc);
            float4 h4 = *(const float4*)(sh + k0 + xc);
            float v0 = fmaf(av.x+bv.x, s4.x, h4.x); v0 = v0>0.f ? v0 : 0.2f*v0;
            float v1 = fmaf(av.y+bv.y, s4.y, h4.y); v1 = v1>0.f ? v1 : 0.2f*v1;
            float v2 = fmaf(av.z+bv.z, s4.z, h4.z); v2 = v2>0.f ? v2 : 0.2f*v2;
            float v3 = fmaf(av.w+bv.w, s4.w, h4.w); v3 = v3>0.f ? v3 : 0.2f*v3;
            uint32_t h, l;
            tf32_split(v0, h, l); XsH[(xc+0)*XST + xr] = h; XsL[(xc+0)*XST + xr] = l;
            tf32_split(v1, h, l); XsH[(xc+1)*XST + xr] = h; XsL[(xc+1)*XST + xr] = l;
            tf32_split(v2, h, l); XsH[(xc+2)*XST + xr] = h; XsL[(xc+2)*XST + xr] = l;
            tf32_split(v3, h, l); XsH[(xc+3)*XST + xr] = h; XsL[(xc+3)*XST + xr] = l;
            if (tid < 256) {
                #pragma unroll
                for (int j = 0; j < NW4; j++) {
                    *(uint4*)&WsH[wk*WST + wc + 4*j] =
                        *(const uint4*)(WH + (size_t)(k0+wk)*CO + wc + 4*j);
                    *(uint4*)&WsL[wk*WST + wc + 4*j] =
                        *(const uint4*)(WL + (size_t)(k0+wk)*CO + wc + 4*j);
                }
            }
            __syncthreads();
            #pragma unroll
            for (int s = 0; s < 2; s++) {
                int kk = s*8;
                int arow = rg*16 + lg;
                uint32_t aH0 = XsH[(kk+lt  )*XST + arow    ];
                uint32_t aH1 = XsH[(kk+lt  )*XST + arow + 8];
                uint32_t aH2 = XsH[(kk+lt+4)*XST + arow    ];
                uint32_t aH3 = XsH[(kk+lt+4)*XST + arow + 8];
                uint32_t aL0 = XsL[(kk+lt  )*XST + arow    ];
                uint32_t aL1 = XsL[(kk+lt  )*XST + arow + 8];
                uint32_t aL2 = XsL[(kk+lt+4)*XST + arow    ];
                uint32_t aL3 = XsL[(kk+lt+4)*XST + arow + 8];
                #pragma unroll
                for (int t = 0; t < NT; t++) {
                    int col = ch*(CO/2) + t*8 + lg;
                    uint32_t bH0 = WsH[(kk+lt  )*WST + col];
                    uint32_t bH1 = WsH[(kk+lt+4)*WST + col];
                    uint32_t bL0 = WsL[(kk+lt  )*WST + col];
                    uint32_t bL1 = WsL[(kk+lt+4)*WST + col];
                    mma_tf32(acc[t], aL0, aL1, aL2, aL3, bH0, bH1);  // lo*hi
                    mma_tf32(acc[t], aH0, aH1, aH2, aH3, bL0, bL1);  // hi*lo
                    mma_tf32(acc[t], aH0, aH1, aH2, aH3, bH0, bH1);  // hi*hi
                }
            }
            __syncthreads();
        }

        // epilogue: smem scatter-max (order-independent) + deterministic stats
        int t0 = nb[rc*128 + rg*16 + lg    ] - b*64;
        int t1 = nb[rc*128 + rg*16 + lg + 8] - b*64;
        float* rp = &redp[rg*2*CO];
        #pragma unroll
        for (int t = 0; t < NT; t++) {
            int cb = ch*(CO/2) + t*8 + 2*lt;
            atomicMax(&maxbuf[t0*CO + cb    ], encf(acc[t][0]));
            atomicMax(&maxbuf[t0*CO + cb + 1], encf(acc[t][1]));
            atomicMax(&maxbuf[t1*CO + cb    ], encf(acc[t][2]));
            atomicMax(&maxbuf[t1*CO + cb + 1], encf(acc[t][3]));
            float s0 = acc[t][0] + acc[t][2];
            float s1 = acc[t][1] + acc[t][3];
            float q0 = acc[t][0]*acc[t][0] + acc[t][2]*acc[t][2];
            float q1 = acc[t][1]*acc[t][1] + acc[t][3]*acc[t][3];
            #pragma unroll
            for (int x = 4; x < 32; x <<= 1) {
                s0 += __shfl_xor_sync(0xffffffffu, s0, x);
                s1 += __shfl_xor_sync(0xffffffffu, s1, x);
                q0 += __shfl_xor_sync(0xffffffffu, q0, x);
                q1 += __shfl_xor_sync(0xffffffffu, q1, x);
            }
            // lane-owned slots: only (this warp, lg==0, this lt) ever touches
            // rp[cb]/rp[cb+1] -> plain read-modify-write, deterministic.
            if (lg == 0) {
                rp[cb        ] += s0;
                rp[cb + 1    ] += s1;
                rp[CO + cb   ] += q0;
                rp[CO + cb +1] += q1;
            }
        }
    }
    __syncthreads();

    for (int i = tid; i < 64*CO; i += 512) {
        int node = b*64 + i/CO, c = i % CO;
        hcat[(size_t)node*HCATC + off + c] = decf(maxbuf[i]);
    }
    // combine 8 row-group partials in fixed order; per-batch store
    for (int c = tid; c < 2*CO; c += 512) {
        float s = 0.f;
        #pragma unroll
        for (int r = 0; r < 8; r++) s += redp[r*2*CO + c];
        part[(size_t)b*2*CO + c] = s;
    }
}

// ---------------- edge pre-act stats, batch-local, deterministic ------------
__global__ void edge_stats_local(const float* __restrict__ A, const float* __restrict__ Bp,
                                 const int* __restrict__ nbr, float* __restrict__ part, int C)
{
    __shared__ float As[64*64];
    __shared__ float Bs[64*64];
    __shared__ int nb[1024];
    int b = blockIdx.x;
    int tid = threadIdx.x;     // 256
    for (int i = tid; i < 1024; i += 256) nb[i] = nbr[b*1024 + i] - b*64;
    for (int c0 = 0; c0 < C; c0 += 64) {
        __syncthreads();
        for (int i = tid; i < 64*64; i += 256) {
            int r = i >> 6, c = i & 63;
            As[i] = A[(size_t)(b*64 + r)*C + c0 + c];
            Bs[i] = Bp[(size_t)(b*64 + r)*C + c0 + c];
        }
        __syncthreads();
        for (int c = tid; c < 64; c += 256) {
            float s = 0.f, q = 0.f;
            #pragma unroll 4
            for (int e = 0; e < 1024; e++) {
                int n = e >> 4;
                float v = As[n*64 + c] + Bs[nb[e]*64 + c];
                s += v; q = fmaf(v, v, q);
            }
            part[(size_t)b*2*C + c0 + c]     = s;
            part[(size_t)b*2*C + C + c0 + c] = q;
        }
    }
}

__global__ void finalize_stats(const float* __restrict__ stats,
                               const float* __restrict__ g, const float* __restrict__ b,
                               float* __restrict__ scale, float* __restrict__ shift,
                               int C, float invR)
{
    int c = blockIdx.x*128 + threadIdx.x;
    if (c >= C) return;
    float m = stats[c] * invR;
    float v = stats[C+c] * invR - m*m;
    float s = g[c] / sqrtf(v + EPSV);
    scale[c] = s;
    shift[c] = b[c] - m*s;
}

__global__ void bn_act(float* __restrict__ X, const float* __restrict__ sc,
                       const float* __restrict__ sh, int total, int C)
{
    int i = blockIdx.x*256 + threadIdx.x;
    if (i >= total) return;
    int c = i % C;
    float v = fmaf(X[i], sc[c], sh[c]);
    X[i] = v > 0.f ? v : 0.2f*v;
}

// ---------------- knn ----------------
__global__ void knn_kernel(const float* __restrict__ H, int ld, int off, int Cin,
                           int* __restrict__ nbr)
{
    extern __shared__ float sm[];
    float* xs  = sm;
    float* sqv = sm + 64*Cin;
    int b = blockIdx.x;
    int n = threadIdx.x;   // 64 threads
    float s = 0.f;
    for (int c = 0; c < Cin; c++) {
        float v = H[(size_t)(b*64 + n)*ld + off + c];
        xs[n*Cin + c] = v;
        s = fmaf(v, v, s);
    }
    sqv[n] = s;
    __syncthreads();
    float d[64];
    for (int m = 0; m < 64; m++) {
        float dot = 0.f;
        const float* xn = &xs[n*Cin];
        const float* xm = &xs[m*Cin];
        for (int c = 0; c < Cin; c++) dot = fmaf(xn[c], xm[c], dot);
        d[m] = sqv[n] - 2.f*dot + sqv[m];
    }
    unsigned long long used = 0ull;
    for (int j = 0; j < KK+1; j++) {
        float best = 3.4e38f; int bm = 0;
        for (int m = 0; m < 64; m++) {
            if (!((used >> m) & 1ull) && d[m] < best) { best = d[m]; bm = m; }
        }
        used |= (1ull << bm);
        if (j > 0) nbr[((size_t)(b*64 + n))*KK + (j-1)] = b*64 + bm;
    }
}

// ---------------- finalize scatter maxima: bn+lrelu on raw max ----------------
__global__ void scatter_fin(float* __restrict__ hcat,
                            const float* __restrict__ sc, const float* __restrict__ sh,
                            int Co, int off)
{
    int i = blockIdx.x*256 + threadIdx.x;
    if (i >= NPTS*Co) return;
    int node = i / Co, c = i % Co;
    size_t p = (size_t)node*HCATC + off + c;
    float raw = hcat[p];
    float out;
    if (isinf(raw) && raw < 0.f) {
        out = 0.f;   // node received no edges
    } else {
        float v = fmaf(raw, sc[c], sh[c]);
        out = v > 0.f ? v : 0.2f*v;
    }
    hcat[p] = out;
}

// ---------------- pooling ----------------
__global__ void pool_kernel(const float* __restrict__ hcat, float* __restrict__ pooled)
{
    int b = blockIdx.x;
    int c = threadIdx.x;  // 448
    float s = 0.f, mx = -3.4e38f;
    for (int n = 0; n < 64; n++) {
        float v = hcat[(size_t)(b*64 + n)*HCATC + c];
        s += v;
        mx = fmaxf(mx, v);
    }
    pooled[(size_t)b*896 + c]       = s * (1.f/64.f);
    pooled[(size_t)b*896 + 448 + c] = mx;
}

// ---------------- host ----------------
static inline int cdiv(int a, int b) { return (a + b - 1) / b; }
static inline int edge_smem(int co) {
    return (2*16*132 + 2*16*(co+8) + 1024 + 64*co + 16*co) * 4;
}

extern "C" void kernel_launch(void* const* d_in, const int* in_sizes, int n_in,
                              void* d_out, int out_size)
{
    const float* x    = (const float*)d_in[0];
    const float* w_in = (const float*)d_in[2];
    const float* g_in = (const float*)d_in[3];
    const float* b_in = (const float*)d_in[4];
    const float* w1a  = (const float*)d_in[5];
    const float* g1a  = (const float*)d_in[6];
    const float* b1a  = (const float*)d_in[7];
    const float* w1b  = (const float*)d_in[8];
    const float* g1b  = (const float*)d_in[9];
    const float* b1b  = (const float*)d_in[10];
    const float* w2a  = (const float*)d_in[11];
    const float* g2a  = (const float*)d_in[12];
    const float* b2a  = (const float*)d_in[13];
    const float* w2b  = (const float*)d_in[14];
    const float* g2b  = (const float*)d_in[15];
    const float* b2b  = (const float*)d_in[16];
    const float* w3a  = (const float*)d_in[17];
    const float* g3a  = (const float*)d_in[18];
    const float* b3a  = (const float*)d_in[19];
    const float* w3b  = (const float*)d_in[20];
    const float* g3b  = (const float*)d_in[21];
    const float* b3b  = (const float*)d_in[22];
    const float* wc1  = (const float*)d_in[23];
    const float* gc1  = (const float*)d_in[24];
    const float* bc1  = (const float*)d_in[25];
    const float* wc2  = (const float*)d_in[26];
    const float* gc2  = (const float*)d_in[27];
    const float* bc2  = (const float*)d_in[28];
    const float* wc3  = (const float*)d_in[29];
    const float* bc3  = (const float*)d_in[30];

    float *h0, *hcat, *A, *Bp, *wB, *stats, *scale, *shift, *part, *pooled, *z1, *z2;
    uint32_t *wH, *wL;
    int* nbr;
    cudaGetSymbolAddress((void**)&h0, g_h0);
    cudaGetSymbolAddress((void**)&hcat, g_hcat);
    cudaGetSymbolAddress((void**)&A, g_A);
    cudaGetSymbolAddress((void**)&Bp, g_Bp);
    cudaGetSymbolAddress((void**)&wB, g_wB);
    cudaGetSymbolAddress((void**)&wH, g_wH);
    cudaGetSymbolAddress((void**)&wL, g_wL);
    cudaGetSymbolAddress((void**)&stats, g_stats);
    cudaGetSymbolAddress((void**)&scale, g_scale);
    cudaGetSymbolAddress((void**)&shift, g_shift);
    cudaGetSymbolAddress((void**)&part, g_part);
    cudaGetSymbolAddress((void**)&pooled, g_pooled);
    cudaGetSymbolAddress((void**)&z1, g_z1);
    cudaGetSymbolAddress((void**)&z2, g_z2);
    cudaGetSymbolAddress((void**)&nbr, g_nbr);

    cudaFuncSetAttribute(edge_mma_batch<64>,  cudaFuncAttributeMaxDynamicSharedMemorySize, edge_smem(64));
    cudaFuncSetAttribute(edge_mma_batch<128>, cudaFuncAttributeMaxDynamicSharedMemorySize, edge_smem(128));
    cudaFuncSetAttribute(edge_mma_batch<256>, cudaFuncAttributeMaxDynamicSharedMemorySize, edge_smem(256));

    // stats arena offsets (sum+sumsq = 2C each)
    const int ST_IN = 0, ST_P1L1 = 128, ST_P2L1 = 256, ST_P1L2 = 384, ST_P2L2 = 640;
    const int ST_P1L3 = 896, ST_P2L3 = 1408, ST_C1 = 1920, ST_C2 = 2944;
    // scale/shift arena offsets (C each)
    const int SS_IN = 0, SS_P1L1 = 64, SS_P2L1 = 128, SS_P1L2 = 192, SS_P2L2 = 320;
    const int SS_P1L3 = 448, SS_P2L3 = 704, SS_C1 = 960, SS_C2 = 1472;

    // 1) input MLP: h0 = lrelu(bn(x @ w_in))
    gemm_bias<<<dim3(1, NPTS/64), 256>>>(x, w_in, nullptr, h0, NPTS, 6, 64, 6, 0, 64, 0);
    col_stats_part<<<dim3(2, 64), dim3(32,8)>>>(h0, part, NPTS, 64, 64, 0);
    reduce_part<<<1, 128>>>(part, stats+ST_IN, 128, 64);
    finalize_stats<<<1, 128>>>(stats+ST_IN, g_in, b_in, scale+SS_IN, shift+SS_IN, 64, 1.f/NPTS);
    bn_act<<<cdiv(NPTS*64,256), 256>>>(h0, scale+SS_IN, shift+SS_IN, NPTS*64, 64);

    // ---- edge conv layers ----
    struct LayerCfg {
        const float* Hin; int ldH, offH, Cin, Cmid, Cout, outOff;
        const float *w1, *g1, *b1, *w2, *g2, *b2;
        int st1, st2, ss1, ss2;
    };
    LayerCfg L[3] = {
        { h0,   64,    0,   64,  64,  64,   0, w1a,g1a,b1a, w1b,g1b,b1b, ST_P1L1,ST_P2L1, SS_P1L1,SS_P2L1 },
        { hcat, HCATC, 0,   64, 128, 128,  64, w2a,g2a,b2a, w2b,g2b,b2b, ST_P1L2,ST_P2L2, SS_P1L2,SS_P2L2 },
        { hcat, HCATC, 64, 128, 256, 256, 192, w3a,g3a,b3a, w3b,g3b,b3b, ST_P1L3,ST_P2L3, SS_P1L3,SS_P2L3 },
    };

    for (int li = 0; li < 3; li++) {
        const LayerCfg& c = L[li];
        knn_kernel<<<BB, 64, (64*c.Cin + 64)*sizeof(float)>>>(c.Hin, c.ldH, c.offH, c.Cin, nbr);
        prep_wb<<<cdiv(c.Cin*c.Cmid,256), 256>>>(c.w1, wB, c.Cin*c.Cmid);
        split_w<<<cdiv(c.Cmid*c.Cout,256), 256>>>(c.w2, wH, wL, c.Cmid*c.Cout);
        gemm_bias<<<dim3(c.Cmid/64, NPTS/64), 256>>>(c.Hin, c.w1 + (size_t)c.Cin*c.Cmid, nullptr,
                                                     A, NPTS, c.Cin, c.Cmid, c.ldH, c.offH, c.Cmid, 0);
        gemm_bias<<<dim3(c.Cmid/64, NPTS/64), 256>>>(c.Hin, wB, nullptr,
                                                     Bp, NPTS, c.Cin, c.Cmid, c.ldH, c.offH, c.Cmid, 0);
        // pre-act stats: per-batch partials (no atomics) + fixed-order reduce
        edge_stats_local<<<BB, 256>>>(A, Bp, nbr, part, c.Cmid);
        reduce_part<<<cdiv(2*c.Cmid,128), 128>>>(part, stats+c.st1, 2*c.Cmid, BB);
        finalize_stats<<<cdiv(c.Cmid,128), 128>>>(stats+c.st1, c.g1, c.b1,
                                                  scale+c.ss1, shift+c.ss1, c.Cmid, 1.f/NEDGE);
        if (c.Cout == 64) {
            edge_mma_batch<64><<<BB, 512, edge_smem(64)>>>(A, Bp, nbr, scale+c.ss1, shift+c.ss1,
                                                  wH, wL, part, hcat, c.Cmid, c.outOff);
        } else if (c.Cout == 128) {
            edge_mma_batch<128><<<BB, 512, edge_smem(128)>>>(A, Bp, nbr, scale+c.ss1, shift+c.ss1,
                                                  wH, wL, part, hcat, c.Cmid, c.outOff);
        } else {
            edge_mma_batch<256><<<BB, 512, edge_smem(256)>>>(A, Bp, nbr, scale+c.ss1, shift+c.ss1,
                                                  wH, wL, part, hcat, c.Cmid, c.outOff);
        }
        reduce_part<<<cdiv(2*c.Cout,128), 128>>>(part, stats+c.st2, 2*c.Cout, BB);
        finalize_stats<<<cdiv(c.Cout,128), 128>>>(stats+c.st2, c.g2, c.b2,
                                                  scale+c.ss2, shift+c.ss2, c.Cout, 1.f/NEDGE);
        scatter_fin<<<cdiv(NPTS*c.Cout,256), 256>>>(hcat, scale+c.ss2, shift+c.ss2, c.Cout, c.outOff);
    }

    // ---- pooling ----
    pool_kernel<<<BB, HCATC>>>(hcat, pooled);

    // ---- classifier ----
    gemm_bias<<<dim3(512/64, BB/64), 256>>>(pooled, wc1, nullptr, z1, BB, 896, 512, 896, 0, 512, 0);
    col_stats_part<<<dim3(16, 8), dim3(32,8)>>>(z1, part, BB, 512, 512, 0);
    reduce_part<<<cdiv(1024,128), 128>>>(part, stats+ST_C1, 1024, 8);
    finalize_stats<<<cdiv(512,128), 128>>>(stats+ST_C1, gc1, bc1, scale+SS_C1, shift+SS_C1, 512, 1.f/BB);
    bn_act<<<cdiv(BB*512,256), 256>>>(z1, scale+SS_C1, shift+SS_C1, BB*512, 512);

    gemm_bias<<<dim3(256/64, BB/64), 256>>>(z1, wc2, nullptr, z2, BB, 512, 256, 512, 0, 256, 0);
    col_stats_part<<<dim3(8, 8), dim3(32,8)>>>(z2, part, BB, 256, 256, 0);
    reduce_part<<<cdiv(512,128), 128>>>(part, stats+ST_C2, 512, 8);
    finalize_stats<<<cdiv(256,128), 128>>>(stats+ST_C2, gc2, bc2, scale+SS_C2, shift+SS_C2, 256, 1.f/BB);
    bn_act<<<cdiv(BB*256,256), 256>>>(z2, scale+SS_C2, shift+SS_C2, BB*256, 256);

    gemm_bias<<<dim3(1, BB/64), 256>>>(z2, wc3, bc3, (float*)d_out, BB, 256, 2, 256, 0, 2, 0);
}

// round 12
// speedup vs baseline: 1.4024x; 1.4024x over previous
#include <cuda_runtime.h>
#include <cuda_bf16.h>
#include <cstdint>

// ---------------------------------------------------------------------------
// DGCNN forward. B=512, N=64, K=16, IN_CH=6.
// DETERMINISTIC: no float atomicAdd anywhere. Edge GEMM2: 3xTF32 mma.sync,
// block=batch, 512 threads, CG column-groups (CG=4 for CO=256 to avoid
// register spills under the 128-reg cap), smem scatter-max.
// ---------------------------------------------------------------------------
#define BB 512
#define NN 64
#define KK 16
#define NPTS (BB*NN)          // 32768
#define NEDGE (NPTS*KK)       // 524288
#define HCATC 448
#define EPSV 1e-5f

// ---------------- static scratch ----------------
__device__ float g_h0[NPTS*64];
__device__ float g_hcat[NPTS*HCATC];
__device__ float g_A[NPTS*256];
__device__ float g_Bp[NPTS*256];
__device__ int   g_nbr[NEDGE];
__device__ float g_wB[256*256];
__device__ uint32_t g_wH[256*256];
__device__ uint32_t g_wL[256*256];
__device__ float g_stats[4096];
__device__ float g_scale[2048];
__device__ float g_shift[2048];
__device__ float g_part[512*512];
__device__ float g_pooled[BB*896];
__device__ float g_z1[BB*512];
__device__ float g_z2[BB*256];

// ---------------- helpers ----------------
__device__ __forceinline__ unsigned encf(float x) {
    unsigned u = __float_as_uint(x);
    return (u & 0x80000000u) ? ~u : (u | 0x80000000u);
}
__device__ __forceinline__ float decf(unsigned u) {
    unsigned b = (u & 0x80000000u) ? (u & 0x7FFFFFFFu) : ~u;
    return __uint_as_float(b);
}
#define ENC_NEGINF 0x007FFFFFu   // encf(-inf)

__device__ __forceinline__ uint32_t f2tf32(float f) {
    uint32_t u; asm("cvt.rna.tf32.f32 %0, %1;" : "=r"(u) : "f"(f)); return u;
}
__device__ __forceinline__ void tf32_split(float x, uint32_t& hi, uint32_t& lo) {
    hi = f2tf32(x);
    lo = f2tf32(x - __uint_as_float(hi));
}
__device__ __forceinline__ void mma_tf32(float* c,
    uint32_t a0, uint32_t a1, uint32_t a2, uint32_t a3, uint32_t b0, uint32_t b1)
{
    asm volatile("mma.sync.aligned.m16n8k8.row.col.f32.tf32.tf32.f32 "
        "{%0,%1,%2,%3}, {%4,%5,%6,%7}, {%8,%9}, {%0,%1,%2,%3};"
        : "+f"(c[0]), "+f"(c[1]), "+f"(c[2]), "+f"(c[3])
        : "r"(a0), "r"(a1), "r"(a2), "r"(a3), "r"(b0), "r"(b1));
}

// wB = w1[0:Cin,:] - w1[Cin:2Cin,:]
__global__ void prep_wb(const float* __restrict__ w1, float* __restrict__ wB, int n) {
    int i = blockIdx.x*256 + threadIdx.x;
    if (i < n) wB[i] = w1[i] - w1[n + i];
}

// precompute tf32 hi/lo split of W
__global__ void split_w(const float* __restrict__ W, uint32_t* __restrict__ WH,
                        uint32_t* __restrict__ WL, int n) {
    int i = blockIdx.x*256 + threadIdx.x;
    if (i < n) {
        uint32_t h, l;
        tf32_split(W[i], h, l);
        WH[i] = h; WL[i] = l;
    }
}

// ---------------- deterministic column stats ----------------
__global__ void col_stats_part(const float* __restrict__ X, float* __restrict__ part,
                               int R, int C, int ld, int off)
{
    int c = blockIdx.x*32 + threadIdx.x;
    int P = gridDim.y;
    float s = 0.f, q = 0.f;
    for (int r = blockIdx.y*8 + threadIdx.y; r < R; r += P*8) {
        float v = X[(size_t)r*ld + off + c];
        s += v; q = fmaf(v, v, q);
    }
    __shared__ float ss[8][33], qq[8][33];
    ss[threadIdx.y][threadIdx.x] = s;
    qq[threadIdx.y][threadIdx.x] = q;
    __syncthreads();
    if (threadIdx.y == 0) {
        #pragma unroll
        for (int y = 1; y < 8; y++) { s += ss[y][threadIdx.x]; q += qq[y][threadIdx.x]; }
        part[(size_t)blockIdx.y*2*C + c]     = s;
        part[(size_t)blockIdx.y*2*C + C + c] = q;
    }
}

__global__ void reduce_part(const float* __restrict__ part, float* __restrict__ stats,
                            int n, int P)
{
    int c = blockIdx.x*128 + threadIdx.x;
    if (c >= n) return;
    float s = 0.f;
    for (int p = 0; p < P; p++) s += part[(size_t)p*n + c];
    stats[c] = s;
}

// ---------------- generic tiled GEMM: Y = X @ W (+bias), fp32 ----------------
__global__ void gemm_bias(const float* __restrict__ X, const float* __restrict__ W,
                          const float* __restrict__ bias, float* __restrict__ Y,
                          int R, int Ci, int Co, int ldx, int xoff, int ldy, int yoff)
{
    __shared__ float Xs[16][68];
    __shared__ float Ws[16][68];
    int row0 = blockIdx.y*64, col0 = blockIdx.x*64;
    int tid = threadIdx.x;
    float acc[4][4] = {};
    for (int k0 = 0; k0 < Ci; k0 += 16) {
        #pragma unroll
        for (int l = 0; l < 4; l++) {
            int i = tid + l*256;
            int r = i >> 4, kk = i & 15;
            int gr = row0 + r, gk = k0 + kk;
            Xs[kk][r] = (gr < R && gk < Ci) ? X[(size_t)gr*ldx + xoff + gk] : 0.f;
        }
        #pragma unroll
        for (int l = 0; l < 4; l++) {
            int i = tid + l*256;
            int kk = i >> 6, c = i & 63;
            int gk = k0 + kk, gc = col0 + c;
            Ws[kk][c] = (gk < Ci && gc < Co) ? W[(size_t)gk*Co + gc] : 0.f;
        }
        __syncthreads();
        int ty = tid >> 4, tx = tid & 15;
        #pragma unroll
        for (int kk = 0; kk < 16; kk++) {
            float4 a = *(const float4*)&Xs[kk][ty*4];
            float4 b = *(const float4*)&Ws[kk][tx*4];
            acc[0][0]=fmaf(a.x,b.x,acc[0][0]); acc[0][1]=fmaf(a.x,b.y,acc[0][1]);
            acc[0][2]=fmaf(a.x,b.z,acc[0][2]); acc[0][3]=fmaf(a.x,b.w,acc[0][3]);
            acc[1][0]=fmaf(a.y,b.x,acc[1][0]); acc[1][1]=fmaf(a.y,b.y,acc[1][1]);
            acc[1][2]=fmaf(a.y,b.z,acc[1][2]); acc[1][3]=fmaf(a.y,b.w,acc[1][3]);
            acc[2][0]=fmaf(a.z,b.x,acc[2][0]); acc[2][1]=fmaf(a.z,b.y,acc[2][1]);
            acc[2][2]=fmaf(a.z,b.z,acc[2][2]); acc[2][3]=fmaf(a.z,b.w,acc[2][3]);
            acc[3][0]=fmaf(a.w,b.x,acc[3][0]); acc[3][1]=fmaf(a.w,b.y,acc[3][1]);
            acc[3][2]=fmaf(a.w,b.z,acc[3][2]); acc[3][3]=fmaf(a.w,b.w,acc[3][3]);
        }
        __syncthreads();
    }
    int ty = tid >> 4, tx = tid & 15;
    #pragma unroll
    for (int i = 0; i < 4; i++) {
        int gr = row0 + ty*4 + i;
        if (gr >= R) continue;
        #pragma unroll
        for (int j = 0; j < 4; j++) {
            int gc = col0 + tx*4 + j;
            if (gc < Co) {
                float v = acc[i][j];
                if (bias) v += bias[gc];
                Y[(size_t)gr*ldy + yoff + gc] = v;
            }
        }
    }
}

// ---------------- edge GEMM2: 3xTF32 mma, block=batch, 512 threads ----------
// 16 warps in CG column-groups x (16/CG) row-groups. Chunk = (16/CG)*16 rows.
// CG=2 for CO<=128 (NT<=8), CG=4 for CO=256 (NT=8, avoids reg spills).
// Deterministic stats: lane-owned smem slots per row-group, fixed-order combine.
template<int CO, int CG>
__global__ void __launch_bounds__(512, 1)
edge_mma_batch(const float* __restrict__ A, const float* __restrict__ Bp,
               const int* __restrict__ nbr,
               const float* __restrict__ sc, const float* __restrict__ sh,
               const uint32_t* __restrict__ WH, const uint32_t* __restrict__ WL,
               float* __restrict__ part,
               float* __restrict__ hcat,
               int Cmid, int off)
{
    constexpr int RG  = 16/CG;          // row groups
    constexpr int CR  = RG*16;          // chunk rows (128 or 64)
    constexpr int NCH = 1024/CR;        // chunks
    constexpr int NT  = CO/(8*CG);      // n-tiles per warp
    constexpr int CW  = CO/CG;          // cols per warp group
    constexpr int WST = CO + 8;
    constexpr int XST = CR + 4;
    extern __shared__ uint32_t smem_u[];
    uint32_t* XsH = smem_u;                      // [16][XST]
    uint32_t* XsL = XsH + 16*XST;
    uint32_t* WsH = XsL + 16*XST;                // [16][WST]
    uint32_t* WsL = WsH + 16*WST;
    int*      nb  = (int*)(WsL + 16*WST);        // [1024]
    unsigned* maxbuf = (unsigned*)(nb + 1024);   // [64][CO]
    float*    redp = (float*)(maxbuf + 64*CO);   // [RG][2*CO]

    int b = blockIdx.x;
    int tid = threadIdx.x;
    int wid = tid >> 5, lane = tid & 31;
    int rg = wid / CG, cw = wid % CG;
    int lt = lane & 3, lg = lane >> 2;

    for (int i = tid; i < 1024; i += 512) nb[i] = nbr[b*1024 + i];
    for (int i = tid; i < 64*CO; i += 512) maxbuf[i] = ENC_NEGINF;
    for (int i = tid; i < RG*2*CO; i += 512) redp[i] = 0.f;
    __syncthreads();

    int xr = tid >> 2;            // row in chunk (valid threads only)
    int xc = (tid & 3) * 4;       // k offset
    int wk = tid >> 4;            // 0..15 (tid<256): W k-row
    int wc = (tid & 15) * (CO/16);

    for (int rc = 0; rc < NCH; rc++) {
        float acc[NT][4];
        #pragma unroll
        for (int t = 0; t < NT; t++) { acc[t][0]=acc[t][1]=acc[t][2]=acc[t][3]=0.f; }

        int n_row = 0, m_row = 0;
        bool xact = (tid < CR*4);
        if (xact) {
            n_row = (b*1024 + rc*CR + xr) >> 4;
            m_row = nb[rc*CR + xr];
        }
        const float* Arow = A + (size_t)n_row*Cmid;
        const float* Brow = Bp + (size_t)m_row*Cmid;

        for (int k0 = 0; k0 < Cmid; k0 += 16) {
            if (xact) {
                float4 av = *(const float4*)(Arow + k0 + xc);
                float4 bv = *(const float4*)(Brow + k0 + xc);
                float4 s4 = *(const float4*)(sc + k0 + xc);
                float4 h4 = *(const float4*)(sh + k0 + xc);
                float v0 = fmaf(av.x+bv.x, s4.x, h4.x); v0 = v0>0.f ? v0 : 0.2f*v0;
                float v1 = fmaf(av.y+bv.y, s4.y, h4.y); v1 = v1>0.f ? v1 : 0.2f*v1;
                float v2 = fmaf(av.z+bv.z, s4.z, h4.z); v2 = v2>0.f ? v2 : 0.2f*v2;
                float v3 = fmaf(av.w+bv.w, s4.w, h4.w); v3 = v3>0.f ? v3 : 0.2f*v3;
                uint32_t h, l;
                tf32_split(v0, h, l); XsH[(xc+0)*XST + xr] = h; XsL[(xc+0)*XST + xr] = l;
                tf32_split(v1, h, l); XsH[(xc+1)*XST + xr] = h; XsL[(xc+1)*XST + xr] = l;
                tf32_split(v2, h, l); XsH[(xc+2)*XST + xr] = h; XsL[(xc+2)*XST + xr] = l;
                tf32_split(v3, h, l); XsH[(xc+3)*XST + xr] = h; XsL[(xc+3)*XST + xr] = l;
            }
            if (tid < 256) {
                #pragma unroll
                for (int j = 0; j < CO/64; j++) {
                    *(uint4*)&WsH[wk*WST + wc + 4*j] =
                        *(const uint4*)(WH + (size_t)(k0+wk)*CO + wc + 4*j);
                    *(uint4*)&WsL[wk*WST + wc + 4*j] =
                        *(const uint4*)(WL + (size_t)(k0+wk)*CO + wc + 4*j);
                }
            }
            __syncthreads();
            #pragma unroll
            for (int s = 0; s < 2; s++) {
                int kk = s*8;
                int arow = rg*16 + lg;
                uint32_t aH0 = XsH[(kk+lt  )*XST + arow    ];
                uint32_t aH1 = XsH[(kk+lt  )*XST + arow + 8];
                uint32_t aH2 = XsH[(kk+lt+4)*XST + arow    ];
                uint32_t aH3 = XsH[(kk+lt+4)*XST + arow + 8];
                uint32_t aL0 = XsL[(kk+lt  )*XST + arow    ];
                uint32_t aL1 = XsL[(kk+lt  )*XST + arow + 8];
                uint32_t aL2 = XsL[(kk+lt+4)*XST + arow    ];
                uint32_t aL3 = XsL[(kk+lt+4)*XST + arow + 8];
                #pragma unroll
                for (int t = 0; t < NT; t++) {
                    int col = cw*CW + t*8 + lg;
                    uint32_t bH0 = WsH[(kk+lt  )*WST + col];
                    uint32_t bH1 = WsH[(kk+lt+4)*WST + col];
                    uint32_t bL0 = WsL[(kk+lt  )*WST + col];
                    uint32_t bL1 = WsL[(kk+lt+4)*WST + col];
                    mma_tf32(acc[t], aL0, aL1, aL2, aL3, bH0, bH1);  // lo*hi
                    mma_tf32(acc[t], aH0, aH1, aH2, aH3, bL0, bL1);  // hi*lo
                    mma_tf32(acc[t], aH0, aH1, aH2, aH3, bH0, bH1);  // hi*hi
                }
            }
            __syncthreads();
        }

        // epilogue: smem scatter-max (order-independent) + deterministic stats
        int t0 = nb[rc*CR + rg*16 + lg    ] - b*64;
        int t1 = nb[rc*CR + rg*16 + lg + 8] - b*64;
        float* rp = &redp[rg*2*CO];
        #pragma unroll
        for (int t = 0; t < NT; t++) {
            int cb = cw*CW + t*8 + 2*lt;
            atomicMax(&maxbuf[t0*CO + cb    ], encf(acc[t][0]));
            atomicMax(&maxbuf[t0*CO + cb + 1], encf(acc[t][1]));
            atomicMax(&maxbuf[t1*CO + cb    ], encf(acc[t][2]));
            atomicMax(&maxbuf[t1*CO + cb + 1], encf(acc[t][3]));
            float s0 = acc[t][0] + acc[t][2];
            float s1 = acc[t][1] + acc[t][3];
            float q0 = acc[t][0]*acc[t][0] + acc[t][2]*acc[t][2];
            float q1 = acc[t][1]*acc[t][1] + acc[t][3]*acc[t][3];
            #pragma unroll
            for (int x = 4; x < 32; x <<= 1) {
                s0 += __shfl_xor_sync(0xffffffffu, s0, x);
                s1 += __shfl_xor_sync(0xffffffffu, s1, x);
                q0 += __shfl_xor_sync(0xffffffffu, q0, x);
                q1 += __shfl_xor_sync(0xffffffffu, q1, x);
            }
            // lane-owned slot: unique (rg, cw, lt) owner -> plain RMW.
            if (lg == 0) {
                rp[cb         ] += s0;
                rp[cb + 1     ] += s1;
                rp[CO + cb    ] += q0;
                rp[CO + cb + 1] += q1;
            }
        }
    }
    __syncthreads();

    for (int i = tid; i < 64*CO; i += 512) {
        int node = b*64 + i/CO, c = i % CO;
        hcat[(size_t)node*HCATC + off + c] = decf(maxbuf[i]);
    }
    // combine RG row-group partials in fixed order; per-batch store
    for (int c = tid; c < 2*CO; c += 512) {
        float s = 0.f;
        #pragma unroll
        for (int r = 0; r < RG; r++) s += redp[r*2*CO + c];
        part[(size_t)b*2*CO + c] = s;
    }
}

// ---------------- edge pre-act stats, batch-local, deterministic ------------
__global__ void edge_stats_local(const float* __restrict__ A, const float* __restrict__ Bp,
                                 const int* __restrict__ nbr, float* __restrict__ part, int C)
{
    __shared__ float As[64*64];
    __shared__ float Bs[64*64];
    __shared__ int nb[1024];
    int b = blockIdx.x;
    int tid = threadIdx.x;     // 256
    for (int i = tid; i < 1024; i += 256) nb[i] = nbr[b*1024 + i] - b*64;
    for (int c0 = 0; c0 < C; c0 += 64) {
        __syncthreads();
        for (int i = tid; i < 64*64; i += 256) {
            int r = i >> 6, c = i & 63;
            As[i] = A[(size_t)(b*64 + r)*C + c0 + c];
            Bs[i] = Bp[(size_t)(b*64 + r)*C + c0 + c];
        }
        __syncthreads();
        for (int c = tid; c < 64; c += 256) {
            float s = 0.f, q = 0.f;
            #pragma unroll 4
            for (int e = 0; e < 1024; e++) {
                int n = e >> 4;
                float v = As[n*64 + c] + Bs[nb[e]*64 + c];
                s += v; q = fmaf(v, v, q);
            }
            part[(size_t)b*2*C + c0 + c]     = s;
            part[(size_t)b*2*C + C + c0 + c] = q;
        }
    }
}

__global__ void finalize_stats(const float* __restrict__ stats,
                               const float* __restrict__ g, const float* __restrict__ b,
                               float* __restrict__ scale, float* __restrict__ shift,
                               int C, float invR)
{
    int c = blockIdx.x*128 + threadIdx.x;
    if (c >= C) return;
    float m = stats[c] * invR;
    float v = stats[C+c] * invR - m*m;
    float s = g[c] / sqrtf(v + EPSV);
    scale[c] = s;
    shift[c] = b[c] - m*s;
}

__global__ void bn_act(float* __restrict__ X, const float* __restrict__ sc,
                       const float* __restrict__ sh, int total, int C)
{
    int i = blockIdx.x*256 + threadIdx.x;
    if (i >= total) return;
    int c = i % C;
    float v = fmaf(X[i], sc[c], sh[c]);
    X[i] = v > 0.f ? v : 0.2f*v;
}

// ---------------- knn ----------------
__global__ void knn_kernel(const float* __restrict__ H, int ld, int off, int Cin,
                           int* __restrict__ nbr)
{
    extern __shared__ float sm[];
    float* xs  = sm;
    float* sqv = sm + 64*Cin;
    int b = blockIdx.x;
    int n = threadIdx.x;   // 64 threads
    float s = 0.f;
    for (int c = 0; c < Cin; c++) {
        float v = H[(size_t)(b*64 + n)*ld + off + c];
        xs[n*Cin + c] = v;
        s = fmaf(v, v, s);
    }
    sqv[n] = s;
    __syncthreads();
    float d[64];
    for (int m = 0; m < 64; m++) {
        float dot = 0.f;
        const float* xn = &xs[n*Cin];
        const float* xm = &xs[m*Cin];
        for (int c = 0; c < Cin; c++) dot = fmaf(xn[c], xm[c], dot);
        d[m] = sqv[n] - 2.f*dot + sqv[m];
    }
    unsigned long long used = 0ull;
    for (int j = 0; j < KK+1; j++) {
        float best = 3.4e38f; int bm = 0;
        for (int m = 0; m < 64; m++) {
            if (!((used >> m) & 1ull) && d[m] < best) { best = d[m]; bm = m; }
        }
        used |= (1ull << bm);
        if (j > 0) nbr[((size_t)(b*64 + n))*KK + (j-1)] = b*64 + bm;
    }
}

// ---------------- finalize scatter maxima: bn+lrelu on raw max ----------------
__global__ void scatter_fin(float* __restrict__ hcat,
                            const float* __restrict__ sc, const float* __restrict__ sh,
                            int Co, int off)
{
    int i = blockIdx.x*256 + threadIdx.x;
    if (i >= NPTS*Co) return;
    int node = i / Co, c = i % Co;
    size_t p = (size_t)node*HCATC + off + c;
    float raw = hcat[p];
    float out;
    if (isinf(raw) && raw < 0.f) {
        out = 0.f;   // node received no edges
    } else {
        float v = fmaf(raw, sc[c], sh[c]);
        out = v > 0.f ? v : 0.2f*v;
    }
    hcat[p] = out;
}

// ---------------- pooling ----------------
__global__ void pool_kernel(const float* __restrict__ hcat, float* __restrict__ pooled)
{
    int b = blockIdx.x;
    int c = threadIdx.x;  // 448
    float s = 0.f, mx = -3.4e38f;
    for (int n = 0; n < 64; n++) {
        float v = hcat[(size_t)(b*64 + n)*HCATC + c];
        s += v;
        mx = fmaxf(mx, v);
    }
    pooled[(size_t)b*896 + c]       = s * (1.f/64.f);
    pooled[(size_t)b*896 + 448 + c] = mx;
}

// ---------------- host ----------------
static inline int cdiv(int a, int b) { return (a + b - 1) / b; }
static inline int edge_smem(int co, int cg) {
    int cr = (16/cg)*16;
    return (2*16*(cr+4) + 2*16*(co+8) + 1024 + 64*co + (16/cg)*2*co) * 4;
}

extern "C" void kernel_launch(void* const* d_in, const int* in_sizes, int n_in,
                              void* d_out, int out_size)
{
    const float* x    = (const float*)d_in[0];
    const float* w_in = (const float*)d_in[2];
    const float* g_in = (const float*)d_in[3];
    const float* b_in = (const float*)d_in[4];
    const float* w1a  = (const float*)d_in[5];
    const float* g1a  = (const float*)d_in[6];
    const float* b1a  = (const float*)d_in[7];
    const float* w1b  = (const float*)d_in[8];
    const float* g1b  = (const float*)d_in[9];
    const float* b1b  = (const float*)d_in[10];
    const float* w2a  = (const float*)d_in[11];
    const float* g2a  = (const float*)d_in[12];
    const float* b2a  = (const float*)d_in[13];
    const float* w2b  = (const float*)d_in[14];
    const float* g2b  = (const float*)d_in[15];
    const float* b2b  = (const float*)d_in[16];
    const float* w3a  = (const float*)d_in[17];
    const float* g3a  = (const float*)d_in[18];
    const float* b3a  = (const float*)d_in[19];
    const float* w3b  = (const float*)d_in[20];
    const float* g3b  = (const float*)d_in[21];
    const float* b3b  = (const float*)d_in[22];
    const float* wc1  = (const float*)d_in[23];
    const float* gc1  = (const float*)d_in[24];
    const float* bc1  = (const float*)d_in[25];
    const float* wc2  = (const float*)d_in[26];
    const float* gc2  = (const float*)d_in[27];
    const float* bc2  = (const float*)d_in[28];
    const float* wc3  = (const float*)d_in[29];
    const float* bc3  = (const float*)d_in[30];

    float *h0, *hcat, *A, *Bp, *wB, *stats, *scale, *shift, *part, *pooled, *z1, *z2;
    uint32_t *wH, *wL;
    int* nbr;
    cudaGetSymbolAddress((void**)&h0, g_h0);
    cudaGetSymbolAddress((void**)&hcat, g_hcat);
    cudaGetSymbolAddress((void**)&A, g_A);
    cudaGetSymbolAddress((void**)&Bp, g_Bp);
    cudaGetSymbolAddress((void**)&wB, g_wB);
    cudaGetSymbolAddress((void**)&wH, g_wH);
    cudaGetSymbolAddress((void**)&wL, g_wL);
    cudaGetSymbolAddress((void**)&stats, g_stats);
    cudaGetSymbolAddress((void**)&scale, g_scale);
    cudaGetSymbolAddress((void**)&shift, g_shift);
    cudaGetSymbolAddress((void**)&part, g_part);
    cudaGetSymbolAddress((void**)&pooled, g_pooled);
    cudaGetSymbolAddress((void**)&z1, g_z1);
    cudaGetSymbolAddress((void**)&z2, g_z2);
    cudaGetSymbolAddress((void**)&nbr, g_nbr);

    cudaFuncSetAttribute(edge_mma_batch<64,2>,  cudaFuncAttributeMaxDynamicSharedMemorySize, edge_smem(64,2));
    cudaFuncSetAttribute(edge_mma_batch<128,2>, cudaFuncAttributeMaxDynamicSharedMemorySize, edge_smem(128,2));
    cudaFuncSetAttribute(edge_mma_batch<256,4>, cudaFuncAttributeMaxDynamicSharedMemorySize, edge_smem(256,4));

    // stats arena offsets (sum+sumsq = 2C each)
    const int ST_IN = 0, ST_P1L1 = 128, ST_P2L1 = 256, ST_P1L2 = 384, ST_P2L2 = 640;
    const int ST_P1L3 = 896, ST_P2L3 = 1408, ST_C1 = 1920, ST_C2 = 2944;
    // scale/shift arena offsets (C each)
    const int SS_IN = 0, SS_P1L1 = 64, SS_P2L1 = 128, SS_P1L2 = 192, SS_P2L2 = 320;
    const int SS_P1L3 = 448, SS_P2L3 = 704, SS_C1 = 960, SS_C2 = 1472;

    // 1) input MLP: h0 = lrelu(bn(x @ w_in))
    gemm_bias<<<dim3(1, NPTS/64), 256>>>(x, w_in, nullptr, h0, NPTS, 6, 64, 6, 0, 64, 0);
    col_stats_part<<<dim3(2, 64), dim3(32,8)>>>(h0, part, NPTS, 64, 64, 0);
    reduce_part<<<1, 128>>>(part, stats+ST_IN, 128, 64);
    finalize_stats<<<1, 128>>>(stats+ST_IN, g_in, b_in, scale+SS_IN, shift+SS_IN, 64, 1.f/NPTS);
    bn_act<<<cdiv(NPTS*64,256), 256>>>(h0, scale+SS_IN, shift+SS_IN, NPTS*64, 64);

    // ---- edge conv layers ----
    struct LayerCfg {
        const float* Hin; int ldH, offH, Cin, Cmid, Cout, outOff;
        const float *w1, *g1, *b1, *w2, *g2, *b2;
        int st1, st2, ss1, ss2;
    };
    LayerCfg L[3] = {
        { h0,   64,    0,   64,  64,  64,   0, w1a,g1a,b1a, w1b,g1b,b1b, ST_P1L1,ST_P2L1, SS_P1L1,SS_P2L1 },
        { hcat, HCATC, 0,   64, 128, 128,  64, w2a,g2a,b2a, w2b,g2b,b2b, ST_P1L2,ST_P2L2, SS_P1L2,SS_P2L2 },
        { hcat, HCATC, 64, 128, 256, 256, 192, w3a,g3a,b3a, w3b,g3b,b3b, ST_P1L3,ST_P2L3, SS_P1L3,SS_P2L3 },
    };

    for (int li = 0; li < 3; li++) {
        const LayerCfg& c = L[li];
        knn_kernel<<<BB, 64, (64*c.Cin + 64)*sizeof(float)>>>(c.Hin, c.ldH, c.offH, c.Cin, nbr);
        prep_wb<<<cdiv(c.Cin*c.Cmid,256), 256>>>(c.w1, wB, c.Cin*c.Cmid);
        split_w<<<cdiv(c.Cmid*c.Cout,256), 256>>>(c.w2, wH, wL, c.Cmid*c.Cout);
        gemm_bias<<<dim3(c.Cmid/64, NPTS/64), 256>>>(c.Hin, c.w1 + (size_t)c.Cin*c.Cmid, nullptr,
                                                     A, NPTS, c.Cin, c.Cmid, c.ldH, c.offH, c.Cmid, 0);
        gemm_bias<<<dim3(c.Cmid/64, NPTS/64), 256>>>(c.Hin, wB, nullptr,
                                                     Bp, NPTS, c.Cin, c.Cmid, c.ldH, c.offH, c.Cmid, 0);
        edge_stats_local<<<BB, 256>>>(A, Bp, nbr, part, c.Cmid);
        reduce_part<<<cdiv(2*c.Cmid,128), 128>>>(part, stats+c.st1, 2*c.Cmid, BB);
        finalize_stats<<<cdiv(c.Cmid,128), 128>>>(stats+c.st1, c.g1, c.b1,
                                                  scale+c.ss1, shift+c.ss1, c.Cmid, 1.f/NEDGE);
        if (c.Cout == 64) {
            edge_mma_batch<64,2><<<BB, 512, edge_smem(64,2)>>>(A, Bp, nbr, scale+c.ss1, shift+c.ss1,
                                                  wH, wL, part, hcat, c.Cmid, c.outOff);
        } else if (c.Cout == 128) {
            edge_mma_batch<128,2><<<BB, 512, edge_smem(128,2)>>>(A, Bp, nbr, scale+c.ss1, shift+c.ss1,
                                                  wH, wL, part, hcat, c.Cmid, c.outOff);
        } else {
            edge_mma_batch<256,4><<<BB, 512, edge_smem(256,4)>>>(A, Bp, nbr, scale+c.ss1, shift+c.ss1,
                                                  wH, wL, part, hcat, c.Cmid, c.outOff);
        }
        reduce_part<<<cdiv(2*c.Cout,128), 128>>>(part, stats+c.st2, 2*c.Cout, BB);
        finalize_stats<<<cdiv(c.Cout,128), 128>>>(stats+c.st2, c.g2, c.b2,
                                                  scale+c.ss2, shift+c.ss2, c.Cout, 1.f/NEDGE);
        scatter_fin<<<cdiv(NPTS*c.Cout,256), 256>>>(hcat, scale+c.ss2, shift+c.ss2, c.Cout, c.outOff);
    }

    // ---- pooling ----
    pool_kernel<<<BB, HCATC>>>(hcat, pooled);

    // ---- classifier ----
    gemm_bias<<<dim3(512/64, BB/64), 256>>>(pooled, wc1, nullptr, z1, BB, 896, 512, 896, 0, 512, 0);
    col_stats_part<<<dim3(16, 8), dim3(32,8)>>>(z1, part, BB, 512, 512, 0);
    reduce_part<<<cdiv(1024,128), 128>>>(part, stats+ST_C1, 1024, 8);
    finalize_stats<<<cdiv(512,128), 128>>>(stats+ST_C1, gc1, bc1, scale+SS_C1, shift+SS_C1, 512, 1.f/BB);
    bn_act<<<cdiv(BB*512,256), 256>>>(z1, scale+SS_C1, shift+SS_C1, BB*512, 512);

    gemm_bias<<<dim3(256/64, BB/64), 256>>>(z1, wc2, nullptr, z2, BB, 512, 256, 512, 0, 256, 0);
    col_stats_part<<<dim3(8, 8), dim3(32,8)>>>(z2, part, BB, 256, 256, 0);
    reduce_part<<<cdiv(512,128), 128>>>(part, stats+ST_C2, 512, 8);
    finalize_stats<<<cdiv(256,128), 128>>>(stats+ST_C2, gc2, bc2, scale+SS_C2, shift+SS_C2, 256, 1.f/BB);
    bn_act<<<cdiv(BB*256,256), 256>>>(z2, scale+SS_C2, shift+SS_C2, BB*256, 256);

    gemm_bias<<<dim3(1, BB/64), 256>>>(z2, wc3, bc3, (float*)d_out, BB, 256, 2, 256, 0, 2, 0);
}

// round 15
// speedup vs baseline: 1.6439x; 1.1722x over previous
#include <cuda_runtime.h>
#include <cuda_bf16.h>
#include <cstdint>

// ---------------------------------------------------------------------------
// DGCNN forward. B=512, N=64, K=16, IN_CH=6.
// DETERMINISTIC: no float atomicAdd anywhere. Edge GEMM2: tf32 mma.sync,
// block=batch, 256 threads (R7 geometry). Layers 1-2: 3-term TF32 (fp32-acc,
// protects knn). Layer 3: 2-term TF32 (feeds no knn; err ~2.4e-4 rel).
// ---------------------------------------------------------------------------
#define BB 512
#define NN 64
#define KK 16
#define NPTS (BB*NN)          // 32768
#define NEDGE (NPTS*KK)       // 524288
#define HCATC 448
#define EPSV 1e-5f

// ---------------- static scratch ----------------
__device__ float g_h0[NPTS*64];
__device__ float g_hcat[NPTS*HCATC];
__device__ float g_A[NPTS*256];
__device__ float g_Bp[NPTS*256];
__device__ int   g_nbr[NEDGE];
__device__ float g_wB[256*256];
__device__ uint32_t g_wH[256*256];
__device__ uint32_t g_wL[256*256];
__device__ float g_stats[4096];
__device__ float g_scale[2048];
__device__ float g_shift[2048];
__device__ float g_part[512*512];
__device__ float g_pooled[BB*896];
__device__ float g_z1[BB*512];
__device__ float g_z2[BB*256];

// ---------------- helpers ----------------
__device__ __forceinline__ unsigned encf(float x) {
    unsigned u = __float_as_uint(x);
    return (u & 0x80000000u) ? ~u : (u | 0x80000000u);
}
__device__ __forceinline__ float decf(unsigned u) {
    unsigned b = (u & 0x80000000u) ? (u & 0x7FFFFFFFu) : ~u;
    return __uint_as_float(b);
}
#define ENC_NEGINF 0x007FFFFFu   // encf(-inf)

__device__ __forceinline__ uint32_t f2tf32(float f) {
    uint32_t u; asm("cvt.rna.tf32.f32 %0, %1;" : "=r"(u) : "f"(f)); return u;
}
__device__ __forceinline__ void tf32_split(float x, uint32_t& hi, uint32_t& lo) {
    hi = f2tf32(x);
    lo = f2tf32(x - __uint_as_float(hi));
}
__device__ __forceinline__ void mma_tf32(float* c,
    uint32_t a0, uint32_t a1, uint32_t a2, uint32_t a3, uint32_t b0, uint32_t b1)
{
    asm volatile("mma.sync.aligned.m16n8k8.row.col.f32.tf32.tf32.f32 "
        "{%0,%1,%2,%3}, {%4,%5,%6,%7}, {%8,%9}, {%0,%1,%2,%3};"
        : "+f"(c[0]), "+f"(c[1]), "+f"(c[2]), "+f"(c[3])
        : "r"(a0), "r"(a1), "r"(a2), "r"(a3), "r"(b0), "r"(b1));
}

// wB = w1[0:Cin,:] - w1[Cin:2Cin,:]
__global__ void prep_wb(const float* __restrict__ w1, float* __restrict__ wB, int n) {
    int i = blockIdx.x*256 + threadIdx.x;
    if (i < n) wB[i] = w1[i] - w1[n + i];
}

// precompute tf32 hi/lo split of W
__global__ void split_w(const float* __restrict__ W, uint32_t* __restrict__ WH,
                        uint32_t* __restrict__ WL, int n) {
    int i = blockIdx.x*256 + threadIdx.x;
    if (i < n) {
        uint32_t h, l;
        tf32_split(W[i], h, l);
        WH[i] = h; WL[i] = l;
    }
}

// ---------------- deterministic column stats ----------------
__global__ void col_stats_part(const float* __restrict__ X, float* __restrict__ part,
                               int R, int C, int ld, int off)
{
    int c = blockIdx.x*32 + threadIdx.x;
    int P = gridDim.y;
    float s = 0.f, q = 0.f;
    for (int r = blockIdx.y*8 + threadIdx.y; r < R; r += P*8) {
        float v = X[(size_t)r*ld + off + c];
        s += v; q = fmaf(v, v, q);
    }
    __shared__ float ss[8][33], qq[8][33];
    ss[threadIdx.y][threadIdx.x] = s;
    qq[threadIdx.y][threadIdx.x] = q;
    __syncthreads();
    if (threadIdx.y == 0) {
        #pragma unroll
        for (int y = 1; y < 8; y++) { s += ss[y][threadIdx.x]; q += qq[y][threadIdx.x]; }
        part[(size_t)blockIdx.y*2*C + c]     = s;
        part[(size_t)blockIdx.y*2*C + C + c] = q;
    }
}

__global__ void reduce_part(const float* __restrict__ part, float* __restrict__ stats,
                            int n, int P)
{
    int c = blockIdx.x*128 + threadIdx.x;
    if (c >= n) return;
    float s = 0.f;
    for (int p = 0; p < P; p++) s += part[(size_t)p*n + c];
    stats[c] = s;
}

// ---------------- generic tiled GEMM: Y = X @ W (+bias), fp32 ----------------
__global__ void gemm_bias(const float* __restrict__ X, const float* __restrict__ W,
                          const float* __restrict__ bias, float* __restrict__ Y,
                          int R, int Ci, int Co, int ldx, int xoff, int ldy, int yoff)
{
    __shared__ float Xs[16][68];
    __shared__ float Ws[16][68];
    int row0 = blockIdx.y*64, col0 = blockIdx.x*64;
    int tid = threadIdx.x;
    float acc[4][4] = {};
    for (int k0 = 0; k0 < Ci; k0 += 16) {
        #pragma unroll
        for (int l = 0; l < 4; l++) {
            int i = tid + l*256;
            int r = i >> 4, kk = i & 15;
            int gr = row0 + r, gk = k0 + kk;
            Xs[kk][r] = (gr < R && gk < Ci) ? X[(size_t)gr*ldx + xoff + gk] : 0.f;
        }
        #pragma unroll
        for (int l = 0; l < 4; l++) {
            int i = tid + l*256;
            int kk = i >> 6, c = i & 63;
            int gk = k0 + kk, gc = col0 + c;
            Ws[kk][c] = (gk < Ci && gc < Co) ? W[(size_t)gk*Co + gc] : 0.f;
        }
        __syncthreads();
        int ty = tid >> 4, tx = tid & 15;
        #pragma unroll
        for (int kk = 0; kk < 16; kk++) {
            float4 a = *(const float4*)&Xs[kk][ty*4];
            float4 b = *(const float4*)&Ws[kk][tx*4];
            acc[0][0]=fmaf(a.x,b.x,acc[0][0]); acc[0][1]=fmaf(a.x,b.y,acc[0][1]);
            acc[0][2]=fmaf(a.x,b.z,acc[0][2]); acc[0][3]=fmaf(a.x,b.w,acc[0][3]);
            acc[1][0]=fmaf(a.y,b.x,acc[1][0]); acc[1][1]=fmaf(a.y,b.y,acc[1][1]);
            acc[1][2]=fmaf(a.y,b.z,acc[1][2]); acc[1][3]=fmaf(a.y,b.w,acc[1][3]);
            acc[2][0]=fmaf(a.z,b.x,acc[2][0]); acc[2][1]=fmaf(a.z,b.y,acc[2][1]);
            acc[2][2]=fmaf(a.z,b.z,acc[2][2]); acc[2][3]=fmaf(a.z,b.w,acc[2][3]);
            acc[3][0]=fmaf(a.w,b.x,acc[3][0]); acc[3][1]=fmaf(a.w,b.y,acc[3][1]);
            acc[3][2]=fmaf(a.w,b.z,acc[3][2]); acc[3][3]=fmaf(a.w,b.w,acc[3][3]);
        }
        __syncthreads();
    }
    int ty = tid >> 4, tx = tid & 15;
    #pragma unroll
    for (int i = 0; i < 4; i++) {
        int gr = row0 + ty*4 + i;
        if (gr >= R) continue;
        #pragma unroll
        for (int j = 0; j < 4; j++) {
            int gc = col0 + tx*4 + j;
            if (gc < Co) {
                float v = acc[i][j];
                if (bias) v += bias[gc];
                Y[(size_t)gr*ldy + yoff + gc] = v;
            }
        }
    }
}

// ---------------- edge GEMM2: tf32 mma, block=batch, 256 threads ------------
// Block b: all 1024 edges of batch b, 16 chunks of 64 edges.
// TERMS=3: aL*bH + aH*bL + aH*bH (fp32-acc). TERMS=2: aL*bH + aH*bH (no WsL).
// Deterministic stats: lane-owned smem slots per row-group, fixed combine.
template<int CO, int TERMS>
__global__ void edge_mma_batch(const float* __restrict__ A, const float* __restrict__ Bp,
                               const int* __restrict__ nbr,
                               const float* __restrict__ sc, const float* __restrict__ sh,
                               const uint32_t* __restrict__ WH, const uint32_t* __restrict__ WL,
                               float* __restrict__ part,
                               float* __restrict__ hcat,
                               int Cmid, int off)
{
    constexpr int NT  = CO/16;     // n-tiles per warp (warp covers CO/2 cols)
    constexpr int WST = CO + 8;
    constexpr int NWS = (TERMS == 3) ? 2 : 1;
    extern __shared__ uint32_t smem_u[];
    uint32_t* XsH = smem_u;                      // [16][68]
    uint32_t* XsL = XsH + 16*68;                 // [16][68]
    uint32_t* WsH = XsL + 16*68;                 // [16][WST]
    uint32_t* WsL = WsH + 16*WST;                // iff TERMS==3
    int*      nb  = (int*)(WsH + NWS*16*WST);    // [1024]
    unsigned* maxbuf = (unsigned*)(nb + 1024);   // [64][CO]
    float*    redp = (float*)(maxbuf + 64*CO);   // [4][2*CO]

    int b = blockIdx.x;
    int tid = threadIdx.x;
    int wid = tid >> 5, lane = tid & 31;
    int rg = wid >> 1, ch = wid & 1;
    int lt = lane & 3, lg = lane >> 2;

    for (int i = tid; i < 1024; i += 256) nb[i] = nbr[b*1024 + i];
    for (int i = tid; i < 64*CO; i += 256) maxbuf[i] = ENC_NEGINF;
    for (int i = tid; i < 4*2*CO; i += 256) redp[i] = 0.f;
    __syncthreads();

    int xr = tid >> 2;            // 0..63: edge row in chunk
    int xc = (tid & 3) * 4;       // k offset 0,4,8,12
    int wk = tid >> 4;            // 0..15: W k-row
    int wc = (tid & 15) * (CO/16);

    for (int rc = 0; rc < 16; rc++) {
        int e0 = b*1024 + rc*64;
        float acc[NT][4];
        #pragma unroll
        for (int t = 0; t < NT; t++) { acc[t][0]=acc[t][1]=acc[t][2]=acc[t][3]=0.f; }

        int n_row = (e0 + xr) >> 4;
        int m_row = nb[rc*64 + xr];
        const float* Arow = A + (size_t)n_row*Cmid;
        const float* Brow = Bp + (size_t)m_row*Cmid;

        for (int k0 = 0; k0 < Cmid; k0 += 16) {
            float4 av = *(const float4*)(Arow + k0 + xc);
            float4 bv = *(const float4*)(Brow + k0 + xc);
            float4 s4 = *(const float4*)(sc + k0 + xc);
            float4 h4 = *(const float4*)(sh + k0 + xc);
            float v0 = fmaf(av.x+bv.x, s4.x, h4.x); v0 = v0>0.f ? v0 : 0.2f*v0;
            float v1 = fmaf(av.y+bv.y, s4.y, h4.y); v1 = v1>0.f ? v1 : 0.2f*v1;
            float v2 = fmaf(av.z+bv.z, s4.z, h4.z); v2 = v2>0.f ? v2 : 0.2f*v2;
            float v3 = fmaf(av.w+bv.w, s4.w, h4.w); v3 = v3>0.f ? v3 : 0.2f*v3;
            uint32_t h, l;
            tf32_split(v0, h, l); XsH[(xc+0)*68 + xr] = h; XsL[(xc+0)*68 + xr] = l;
            tf32_split(v1, h, l); XsH[(xc+1)*68 + xr] = h; XsL[(xc+1)*68 + xr] = l;
            tf32_split(v2, h, l); XsH[(xc+2)*68 + xr] = h; XsL[(xc+2)*68 + xr] = l;
            tf32_split(v3, h, l); XsH[(xc+3)*68 + xr] = h; XsL[(xc+3)*68 + xr] = l;
            #pragma unroll
            for (int j = 0; j < CO/64; j++) {
                *(uint4*)&WsH[wk*WST + wc + 4*j] =
                    *(const uint4*)(WH + (size_t)(k0+wk)*CO + wc + 4*j);
                if constexpr (TERMS == 3)
                    *(uint4*)&WsL[wk*WST + wc + 4*j] =
                        *(const uint4*)(WL + (size_t)(k0+wk)*CO + wc + 4*j);
            }
            __syncthreads();
            #pragma unroll
            for (int s = 0; s < 2; s++) {
                int kk = s*8;
                int arow = rg*16 + lg;
                uint32_t aH0 = XsH[(kk+lt  )*68 + arow    ];
                uint32_t aH1 = XsH[(kk+lt  )*68 + arow + 8];
                uint32_t aH2 = XsH[(kk+lt+4)*68 + arow    ];
                uint32_t aH3 = XsH[(kk+lt+4)*68 + arow + 8];
                uint32_t aL0 = XsL[(kk+lt  )*68 + arow    ];
                uint32_t aL1 = XsL[(kk+lt  )*68 + arow + 8];
                uint32_t aL2 = XsL[(kk+lt+4)*68 + arow    ];
                uint32_t aL3 = XsL[(kk+lt+4)*68 + arow + 8];
                #pragma unroll
                for (int t = 0; t < NT; t++) {
                    int col = ch*(CO/2) + t*8 + lg;
                    uint32_t bH0 = WsH[(kk+lt  )*WST + col];
                    uint32_t bH1 = WsH[(kk+lt+4)*WST + col];
                    mma_tf32(acc[t], aL0, aL1, aL2, aL3, bH0, bH1);      // lo*hi
                    if constexpr (TERMS == 3) {
                        uint32_t bL0 = WsL[(kk+lt  )*WST + col];
                        uint32_t bL1 = WsL[(kk+lt+4)*WST + col];
                        mma_tf32(acc[t], aH0, aH1, aH2, aH3, bL0, bL1);  // hi*lo
                    }
                    mma_tf32(acc[t], aH0, aH1, aH2, aH3, bH0, bH1);      // hi*hi
                }
            }
            __syncthreads();
        }

        // epilogue: smem scatter-max (order-independent) + deterministic stats
        int t0 = nb[rc*64 + rg*16 + lg    ] - b*64;
        int t1 = nb[rc*64 + rg*16 + lg + 8] - b*64;
        float* rp = &redp[rg*2*CO];
        #pragma unroll
        for (int t = 0; t < NT; t++) {
            int cb = ch*(CO/2) + t*8 + 2*lt;
            atomicMax(&maxbuf[t0*CO + cb    ], encf(acc[t][0]));
            atomicMax(&maxbuf[t0*CO + cb + 1], encf(acc[t][1]));
            atomicMax(&maxbuf[t1*CO + cb    ], encf(acc[t][2]));
            atomicMax(&maxbuf[t1*CO + cb + 1], encf(acc[t][3]));
            float s0 = acc[t][0] + acc[t][2];
            float s1 = acc[t][1] + acc[t][3];
            float q0 = acc[t][0]*acc[t][0] + acc[t][2]*acc[t][2];
            float q1 = acc[t][1]*acc[t][1] + acc[t][3]*acc[t][3];
            #pragma unroll
            for (int x = 4; x < 32; x <<= 1) {
                s0 += __shfl_xor_sync(0xffffffffu, s0, x);
                s1 += __shfl_xor_sync(0xffffffffu, s1, x);
                q0 += __shfl_xor_sync(0xffffffffu, q0, x);
                q1 += __shfl_xor_sync(0xffffffffu, q1, x);
            }
            // lane-owned slot: unique (rg, ch, lt) owner -> plain RMW.
            if (lg == 0) {
                rp[cb         ] += s0;
                rp[cb + 1     ] += s1;
                rp[CO + cb    ] += q0;
                rp[CO + cb + 1] += q1;
            }
        }
    }
    __syncthreads();

    for (int i = tid; i < 64*CO; i += 256) {
        int node = b*64 + i/CO, c = i % CO;
        hcat[(size_t)node*HCATC + off + c] = decf(maxbuf[i]);
    }
    // combine 4 row-group partials in fixed order; per-batch store
    for (int c = tid; c < 2*CO; c += 256) {
        float s = 0.f;
        #pragma unroll
        for (int r = 0; r < 4; r++) s += redp[r*2*CO + c];
        part[(size_t)b*2*CO + c] = s;
    }
}

// ---------------- edge pre-act stats, batch-local, deterministic ------------
__global__ void edge_stats_local(const float* __restrict__ A, const float* __restrict__ Bp,
                                 const int* __restrict__ nbr, float* __restrict__ part, int C)
{
    __shared__ float As[64*64];
    __shared__ float Bs[64*64];
    __shared__ int nb[1024];
    int b = blockIdx.x;
    int tid = threadIdx.x;     // 256
    for (int i = tid; i < 1024; i += 256) nb[i] = nbr[b*1024 + i] - b*64;
    for (int c0 = 0; c0 < C; c0 += 64) {
        __syncthreads();
        for (int i = tid; i < 64*64; i += 256) {
            int r = i >> 6, c = i & 63;
            As[i] = A[(size_t)(b*64 + r)*C + c0 + c];
            Bs[i] = Bp[(size_t)(b*64 + r)*C + c0 + c];
        }
        __syncthreads();
        for (int c = tid; c < 64; c += 256) {
            float s = 0.f, q = 0.f;
            #pragma unroll 4
            for (int e = 0; e < 1024; e++) {
                int n = e >> 4;
                float v = As[n*64 + c] + Bs[nb[e]*64 + c];
                s += v; q = fmaf(v, v, q);
            }
            part[(size_t)b*2*C + c0 + c]     = s;
            part[(size_t)b*2*C + C + c0 + c] = q;
        }
    }
}

__global__ void finalize_stats(const float* __restrict__ stats,
                               const float* __restrict__ g, const float* __restrict__ b,
                               float* __restrict__ scale, float* __restrict__ shift,
                               int C, float invR)
{
    int c = blockIdx.x*128 + threadIdx.x;
    if (c >= C) return;
    float m = stats[c] * invR;
    float v = stats[C+c] * invR - m*m;
    float s = g[c] / sqrtf(v + EPSV);
    scale[c] = s;
    shift[c] = b[c] - m*s;
}

__global__ void bn_act(float* __restrict__ X, const float* __restrict__ sc,
                       const float* __restrict__ sh, int total, int C)
{
    int i = blockIdx.x*256 + threadIdx.x;
    if (i >= total) return;
    int c = i % C;
    float v = fmaf(X[i], sc[c], sh[c]);
    X[i] = v > 0.f ? v : 0.2f*v;
}

// ---------------- knn ----------------
__global__ void knn_kernel(const float* __restrict__ H, int ld, int off, int Cin,
                           int* __restrict__ nbr)
{
    extern __shared__ float sm[];
    float* xs  = sm;
    float* sqv = sm + 64*Cin;
    int b = blockIdx.x;
    int n = threadIdx.x;   // 64 threads
    float s = 0.f;
    for (int c = 0; c < Cin; c++) {
        float v = H[(size_t)(b*64 + n)*ld + off + c];
        xs[n*Cin + c] = v;
        s = fmaf(v, v, s);
    }
    sqv[n] = s;
    __syncthreads();
    float d[64];
    for (int m = 0; m < 64; m++) {
        float dot = 0.f;
        const float* xn = &xs[n*Cin];
        const float* xm = &xs[m*Cin];
        for (int c = 0; c < Cin; c++) dot = fmaf(xn[c], xm[c], dot);
        d[m] = sqv[n] - 2.f*dot + sqv[m];
    }
    unsigned long long used = 0ull;
    for (int j = 0; j < KK+1; j++) {
        float best = 3.4e38f; int bm = 0;
        for (int m = 0; m < 64; m++) {
            if (!((used >> m) & 1ull) && d[m] < best) { best = d[m]; bm = m; }
        }
        used |= (1ull << bm);
        if (j > 0) nbr[((size_t)(b*64 + n))*KK + (j-1)] = b*64 + bm;
    }
}

// ---------------- finalize scatter maxima: bn+lrelu on raw max ----------------
__global__ void scatter_fin(float* __restrict__ hcat,
                            const float* __restrict__ sc, const float* __restrict__ sh,
                            int Co, int off)
{
    int i = blockIdx.x*256 + threadIdx.x;
    if (i >= NPTS*Co) return;
    int node = i / Co, c = i % Co;
    size_t p = (size_t)node*HCATC + off + c;
    float raw = hcat[p];
    float out;
    if (isinf(raw) && raw < 0.f) {
        out = 0.f;   // node received no edges
    } else {
        float v = fmaf(raw, sc[c], sh[c]);
        out = v > 0.f ? v : 0.2f*v;
    }
    hcat[p] = out;
}

// ---------------- pooling ----------------
__global__ void pool_kernel(const float* __restrict__ hcat, float* __restrict__ pooled)
{
    int b = blockIdx.x;
    int c = threadIdx.x;  // 448
    float s = 0.f, mx = -3.4e38f;
    for (int n = 0; n < 64; n++) {
        float v = hcat[(size_t)(b*64 + n)*HCATC + c];
        s += v;
        mx = fmaxf(mx, v);
    }
    pooled[(size_t)b*896 + c]       = s * (1.f/64.f);
    pooled[(size_t)b*896 + 448 + c] = mx;
}

// ---------------- host ----------------
static inline int cdiv(int a, int b) { return (a + b - 1) / b; }
static inline int edge_smem(int co, int terms) {
    int nws = (terms == 3) ? 2 : 1;
    return (2*16*68 + nws*16*(co+8) + 1024 + 64*co + 8*co) * 4;
}

extern "C" void kernel_launch(void* const* d_in, const int* in_sizes, int n_in,
                              void* d_out, int out_size)
{
    const float* x    = (const float*)d_in[0];
    const float* w_in = (const float*)d_in[2];
    const float* g_in = (const float*)d_in[3];
    const float* b_in = (const float*)d_in[4];
    const float* w1a  = (const float*)d_in[5];
    const float* g1a  = (const float*)d_in[6];
    const float* b1a  = (const float*)d_in[7];
    const float* w1b  = (const float*)d_in[8];
    const float* g1b  = (const float*)d_in[9];
    const float* b1b  = (const float*)d_in[10];
    const float* w2a  = (const float*)d_in[11];
    const float* g2a  = (const float*)d_in[12];
    const float* b2a  = (const float*)d_in[13];
    const float* w2b  = (const float*)d_in[14];
    const float* g2b  = (const float*)d_in[15];
    const float* b2b  = (const float*)d_in[16];
    const float* w3a  = (const float*)d_in[17];
    const float* g3a  = (const float*)d_in[18];
    const float* b3a  = (const float*)d_in[19];
    const float* w3b  = (const float*)d_in[20];
    const float* g3b  = (const float*)d_in[21];
    const float* b3b  = (const float*)d_in[22];
    const float* wc1  = (const float*)d_in[23];
    const float* gc1  = (const float*)d_in[24];
    const float* bc1  = (const float*)d_in[25];
    const float* wc2  = (const float*)d_in[26];
    const float* gc2  = (const float*)d_in[27];
    const float* bc2  = (const float*)d_in[28];
    const float* wc3  = (const float*)d_in[29];
    const float* bc3  = (const float*)d_in[30];

    float *h0, *hcat, *A, *Bp, *wB, *stats, *scale, *shift, *part, *pooled, *z1, *z2;
    uint32_t *wH, *wL;
    int* nbr;
    cudaGetSymbolAddress((void**)&h0, g_h0);
    cudaGetSymbolAddress((void**)&hcat, g_hcat);
    cudaGetSymbolAddress((void**)&A, g_A);
    cudaGetSymbolAddress((void**)&Bp, g_Bp);
    cudaGetSymbolAddress((void**)&wB, g_wB);
    cudaGetSymbolAddress((void**)&wH, g_wH);
    cudaGetSymbolAddress((void**)&wL, g_wL);
    cudaGetSymbolAddress((void**)&stats, g_stats);
    cudaGetSymbolAddress((void**)&scale, g_scale);
    cudaGetSymbolAddress((void**)&shift, g_shift);
    cudaGetSymbolAddress((void**)&part, g_part);
    cudaGetSymbolAddress((void**)&pooled, g_pooled);
    cudaGetSymbolAddress((void**)&z1, g_z1);
    cudaGetSymbolAddress((void**)&z2, g_z2);
    cudaGetSymbolAddress((void**)&nbr, g_nbr);

    cudaFuncSetAttribute(edge_mma_batch<64,3>,  cudaFuncAttributeMaxDynamicSharedMemorySize, edge_smem(64,3));
    cudaFuncSetAttribute(edge_mma_batch<128,3>, cudaFuncAttributeMaxDynamicSharedMemorySize, edge_smem(128,3));
    cudaFuncSetAttribute(edge_mma_batch<256,2>, cudaFuncAttributeMaxDynamicSharedMemorySize, edge_smem(256,2));

    // stats arena offsets (sum+sumsq = 2C each)
    const int ST_IN = 0, ST_P1L1 = 128, ST_P2L1 = 256, ST_P1L2 = 384, ST_P2L2 = 640;
    const int ST_P1L3 = 896, ST_P2L3 = 1408, ST_C1 = 1920, ST_C2 = 2944;
    // scale/shift arena offsets (C each)
    const int SS_IN = 0, SS_P1L1 = 64, SS_P2L1 = 128, SS_P1L2 = 192, SS_P2L2 = 320;
    const int SS_P1L3 = 448, SS_P2L3 = 704, SS_C1 = 960, SS_C2 = 1472;

    // 1) input MLP: h0 = lrelu(bn(x @ w_in))
    gemm_bias<<<dim3(1, NPTS/64), 256>>>(x, w_in, nullptr, h0, NPTS, 6, 64, 6, 0, 64, 0);
    col_stats_part<<<dim3(2, 64), dim3(32,8)>>>(h0, part, NPTS, 64, 64, 0);
    reduce_part<<<1, 128>>>(part, stats+ST_IN, 128, 64);
    finalize_stats<<<1, 128>>>(stats+ST_IN, g_in, b_in, scale+SS_IN, shift+SS_IN, 64, 1.f/NPTS);
    bn_act<<<cdiv(NPTS*64,256), 256>>>(h0, scale+SS_IN, shift+SS_IN, NPTS*64, 64);

    // ---- edge conv layers ----
    struct LayerCfg {
        const float* Hin; int ldH, offH, Cin, Cmid, Cout, outOff;
        const float *w1, *g1, *b1, *w2, *g2, *b2;
        int st1, st2, ss1, ss2;
    };
    LayerCfg L[3] = {
        { h0,   64,    0,   64,  64,  64,   0, w1a,g1a,b1a, w1b,g1b,b1b, ST_P1L1,ST_P2L1, SS_P1L1,SS_P2L1 },
        { hcat, HCATC, 0,   64, 128, 128,  64, w2a,g2a,b2a, w2b,g2b,b2b, ST_P1L2,ST_P2L2, SS_P1L2,SS_P2L2 },
        { hcat, HCATC, 64, 128, 256, 256, 192, w3a,g3a,b3a, w3b,g3b,b3b, ST_P1L3,ST_P2L3, SS_P1L3,SS_P2L3 },
    };

    for (int li = 0; li < 3; li++) {
        const LayerCfg& c = L[li];
        knn_kernel<<<BB, 64, (64*c.Cin + 64)*sizeof(float)>>>(c.Hin, c.ldH, c.offH, c.Cin, nbr);
        prep_wb<<<cdiv(c.Cin*c.Cmid,256), 256>>>(c.w1, wB, c.Cin*c.Cmid);
        split_w<<<cdiv(c.Cmid*c.Cout,256), 256>>>(c.w2, wH, wL, c.Cmid*c.Cout);
        gemm_bias<<<dim3(c.Cmid/64, NPTS/64), 256>>>(c.Hin, c.w1 + (size_t)c.Cin*c.Cmid, nullptr,
                                                     A, NPTS, c.Cin, c.Cmid, c.ldH, c.offH, c.Cmid, 0);
        gemm_bias<<<dim3(c.Cmid/64, NPTS/64), 256>>>(c.Hin, wB, nullptr,
                                                     Bp, NPTS, c.Cin, c.Cmid, c.ldH, c.offH, c.Cmid, 0);
        edge_stats_local<<<BB, 256>>>(A, Bp, nbr, part, c.Cmid);
        reduce_part<<<cdiv(2*c.Cmid,128), 128>>>(part, stats+c.st1, 2*c.Cmid, BB);
        finalize_stats<<<cdiv(c.Cmid,128), 128>>>(stats+c.st1, c.g1, c.b1,
                                                  scale+c.ss1, shift+c.ss1, c.Cmid, 1.f/NEDGE);
        if (c.Cout == 64) {
            edge_mma_batch<64,3><<<BB, 256, edge_smem(64,3)>>>(A, Bp, nbr, scale+c.ss1, shift+c.ss1,
                                                  wH, wL, part, hcat, c.Cmid, c.outOff);
        } else if (c.Cout == 128) {
            edge_mma_batch<128,3><<<BB, 256, edge_smem(128,3)>>>(A, Bp, nbr, scale+c.ss1, shift+c.ss1,
                                                  wH, wL, part, hcat, c.Cmid, c.outOff);
        } else {
            edge_mma_batch<256,2><<<BB, 256, edge_smem(256,2)>>>(A, Bp, nbr, scale+c.ss1, shift+c.ss1,
                                                  wH, wL, part, hcat, c.Cmid, c.outOff);
        }
        reduce_part<<<cdiv(2*c.Cout,128), 128>>>(part, stats+c.st2, 2*c.Cout, BB);
        finalize_stats<<<cdiv(c.Cout,128), 128>>>(stats+c.st2, c.g2, c.b2,
                                                  scale+c.ss2, shift+c.ss2, c.Cout, 1.f/NEDGE);
        scatter_fin<<<cdiv(NPTS*c.Cout,256), 256>>>(hcat, scale+c.ss2, shift+c.ss2, c.Cout, c.outOff);
    }

    // ---- pooling ----
    pool_kernel<<<BB, HCATC>>>(hcat, pooled);

    // ---- classifier ----
    gemm_bias<<<dim3(512/64, BB/64), 256>>>(pooled, wc1, nullptr, z1, BB, 896, 512, 896, 0, 512, 0);
    col_stats_part<<<dim3(16, 8), dim3(32,8)>>>(z1, part, BB, 512, 512, 0);
    reduce_part<<<cdiv(1024,128), 128>>>(part, stats+ST_C1, 1024, 8);
    finalize_stats<<<cdiv(512,128), 128>>>(stats+ST_C1, gc1, bc1, scale+SS_C1, shift+SS_C1, 512, 1.f/BB);
    bn_act<<<cdiv(BB*512,256), 256>>>(z1, scale+SS_C1, shift+SS_C1, BB*512, 512);

    gemm_bias<<<dim3(256/64, BB/64), 256>>>(z1, wc2, nullptr, z2, BB, 512, 256, 512, 0, 256, 0);
    col_stats_part<<<dim3(8, 8), dim3(32,8)>>>(z2, part, BB, 256, 256, 0);
    reduce_part<<<cdiv(512,128), 128>>>(part, stats+ST_C2, 512, 8);
    finalize_stats<<<cdiv(256,128), 128>>>(stats+ST_C2, gc2, bc2, scale+SS_C2, shift+SS_C2, 256, 1.f/BB);
    bn_act<<<cdiv(BB*256,256), 256>>>(z2, scale+SS_C2, shift+SS_C2, BB*256, 256);

    gemm_bias<<<dim3(1, BB/64), 256>>>(z2, wc3, bc3, (float*)d_out, BB, 256, 2, 256, 0, 2, 0);
}